// round 2
// baseline (speedup 1.0000x reference)
#include <cuda_runtime.h>
#include <cuda_bf16.h>
#include <math.h>

#define Bb 2
#define Tt 1024
#define Cc 512
#define Hh 8
#define KVh 2
#define HD 64
#define Ll 2
#define Ee 8
#define TOPK 2
#define Vv 32000
#define Nn (Bb*Tt)        // 2048 tokens
#define KVD (KVh*HD)      // 128
#define EPSf 1e-6f

// ---------------- scratch (device globals; no allocation allowed) ----------------
__device__ float g_h[Nn*Cc];
__device__ float g_xn[Nn*Cc];
__device__ float g_q[Nn*Cc];
__device__ float g_k[Nn*KVD];
__device__ float g_v[Nn*KVD];
__device__ float g_att[Nn*Cc];
__device__ float g_proj[Nn*Cc];
__device__ float g_moe[Ee*Nn*Cc];
__device__ int   g_sel[Nn*TOPK];
__device__ float g_gw[Nn*TOPK];

// ---------------- embedding ----------------
__global__ void embed_kernel(const int* __restrict__ ids,
                             const float* __restrict__ tok,
                             const float* __restrict__ pos) {
    int idx = blockIdx.x * blockDim.x + threadIdx.x;
    if (idx >= Nn*Cc) return;
    int n = idx / Cc, c = idx - n*Cc;
    int t = n % Tt;
    g_h[idx] = tok[(size_t)ids[n]*Cc + c] + pos[(size_t)t*Cc + c];
}

// ---------------- rmsnorm (block per token) ----------------
__global__ void rmsnorm_kernel(const float* __restrict__ x,
                               const float* __restrict__ w,
                               float* __restrict__ y) {
    int n = blockIdx.x;
    const float* xr = x + (size_t)n*Cc;
    __shared__ float red[256];
    float s = 0.f;
    for (int c = threadIdx.x; c < Cc; c += 256) { float v = xr[c]; s += v*v; }
    red[threadIdx.x] = s; __syncthreads();
    for (int o = 128; o > 0; o >>= 1) {
        if (threadIdx.x < o) red[threadIdx.x] += red[threadIdx.x + o];
        __syncthreads();
    }
    float inv = rsqrtf(red[0] / (float)Cc + EPSf);
    for (int c = threadIdx.x; c < Cc; c += 256)
        y[(size_t)n*Cc + c] = xr[c] * inv * w[c];
}

// ---------------- tiled SGEMM (NT): C[M,N] = A[M,K] * B[N,K]^T ----------------
// 128x128 tile, BK=16, 256 threads, 8x8 per-thread microtile.
// Batched over blockIdx.z via strideB / strideC.
__global__ __launch_bounds__(256)
void sgemm_nt(const float* __restrict__ A, const float* __restrict__ Bm,
              float* __restrict__ Cm, int M, int N, int K,
              size_t strideB, size_t strideC) {
    Bm += (size_t)blockIdx.z * strideB;
    Cm += (size_t)blockIdx.z * strideC;
    const int BM = 128, BN = 128, BK = 16;
    __shared__ float As[BK][BM + 4];
    __shared__ float Bs[BK][BN + 4];
    int tid = threadIdx.x;
    int tx = tid & 15, ty = tid >> 4;
    int row0 = blockIdx.y * BM, col0 = blockIdx.x * BN;
    float acc[8][8];
    #pragma unroll
    for (int i = 0; i < 8; i++)
        #pragma unroll
        for (int j = 0; j < 8; j++) acc[i][j] = 0.f;

    for (int k0 = 0; k0 < K; k0 += BK) {
        #pragma unroll
        for (int i = 0; i < 8; i++) {
            int idx = tid + i*256;
            int m = idx >> 4, kk = idx & 15;
            int gr = row0 + m;
            As[kk][m] = (gr < M) ? A[(size_t)gr*K + k0 + kk] : 0.f;
        }
        #pragma unroll
        for (int i = 0; i < 8; i++) {
            int idx = tid + i*256;
            int nn = idx >> 4, kk = idx & 15;
            int gc = col0 + nn;
            Bs[kk][nn] = (gc < N) ? Bm[(size_t)gc*K + k0 + kk] : 0.f;
        }
        __syncthreads();
        #pragma unroll
        for (int kk = 0; kk < BK; kk++) {
            float ra[8], rb[8];
            #pragma unroll
            for (int i = 0; i < 8; i++) ra[i] = As[kk][ty*8 + i];
            #pragma unroll
            for (int j = 0; j < 8; j++) rb[j] = Bs[kk][tx*8 + j];
            #pragma unroll
            for (int i = 0; i < 8; i++)
                #pragma unroll
                for (int j = 0; j < 8; j++) acc[i][j] += ra[i]*rb[j];
        }
        __syncthreads();
    }
    #pragma unroll
    for (int i = 0; i < 8; i++) {
        int r = row0 + ty*8 + i;
        if (r >= M) continue;
        #pragma unroll
        for (int j = 0; j < 8; j++) {
            int c = col0 + tx*8 + j;
            if (c < N) Cm[(size_t)r*N + c] = acc[i][j];
        }
    }
}

// ---------------- causal GQA attention: block per (q, head, batch) ----------------
__global__ void attn_kernel() {
    int qp = blockIdx.x, hh = blockIdx.y, b = blockIdx.z;
    int kvh = hh / (Hh / KVh);
    __shared__ float qs[HD];
    __shared__ float sc[Tt];
    __shared__ float red[128];
    int tid = threadIdx.x;

    const float* qrow = g_q + ((size_t)(b*Tt + qp))*Cc + hh*HD;
    if (tid < HD) qs[tid] = qrow[tid];
    __syncthreads();

    int nk = qp + 1;
    float lmax = -1e30f;
    for (int k = tid; k < nk; k += 128) {
        const float* kr = g_k + ((size_t)(b*Tt + k))*KVD + kvh*HD;
        float d = 0.f;
        #pragma unroll
        for (int i = 0; i < HD; i++) d += qs[i]*kr[i];
        d *= 0.125f;  // 1/sqrt(64)
        sc[k] = d;
        lmax = fmaxf(lmax, d);
    }
    red[tid] = lmax; __syncthreads();
    for (int o = 64; o > 0; o >>= 1) {
        if (tid < o) red[tid] = fmaxf(red[tid], red[tid + o]);
        __syncthreads();
    }
    float m = red[0];
    __syncthreads();

    float ls = 0.f;
    for (int k = tid; k < nk; k += 128) {
        float e = expf(sc[k] - m);
        sc[k] = e;
        ls += e;
    }
    red[tid] = ls; __syncthreads();
    for (int o = 64; o > 0; o >>= 1) {
        if (tid < o) red[tid] += red[tid + o];
        __syncthreads();
    }
    float inv = 1.f / red[0];
    __syncthreads();

    if (tid < HD) {
        float acc = 0.f;
        const float* vbase = g_v + (size_t)b*Tt*KVD + kvh*HD + tid;
        for (int k = 0; k < nk; k++) acc += sc[k] * vbase[(size_t)k*KVD];
        g_att[((size_t)(b*Tt + qp))*Cc + hh*HD + tid] = acc * inv;
    }
}

// ---------------- residual add ----------------
__global__ void add_kernel(float* __restrict__ a, const float* __restrict__ b, int n) {
    int idx = blockIdx.x*blockDim.x + threadIdx.x;
    if (idx < n) a[idx] += b[idx];
}

// ---------------- gating: warp per token, top-2 + softmax ----------------
__global__ void gate_kernel(const float* __restrict__ xn, const float* __restrict__ gw) {
    int warp = (blockIdx.x*blockDim.x + threadIdx.x) >> 5;
    int lane = threadIdx.x & 31;
    if (warp >= Nn) return;
    const float* xr = xn + (size_t)warp*Cc;
    float logits[Ee];
    #pragma unroll
    for (int e = 0; e < Ee; e++) {
        float s = 0.f;
        for (int c = lane; c < Cc; c += 32) s += xr[c]*gw[(size_t)e*Cc + c];
        #pragma unroll
        for (int o = 16; o > 0; o >>= 1) s += __shfl_down_sync(0xffffffffu, s, o);
        logits[e] = __shfl_sync(0xffffffffu, s, 0);
    }
    if (lane == 0) {
        int b0 = 0;
        #pragma unroll
        for (int e = 1; e < Ee; e++) if (logits[e] > logits[b0]) b0 = e;
        int b1 = -1;
        #pragma unroll
        for (int e = 0; e < Ee; e++) {
            if (e == b0) continue;
            if (b1 < 0 || logits[e] > logits[b1]) b1 = e;
        }
        float mm = logits[b0];
        float e0 = expf(logits[b0] - mm), e1 = expf(logits[b1] - mm);
        float s = e0 + e1;
        g_sel[warp*2]   = b0;  g_sel[warp*2+1] = b1;
        g_gw[warp*2]    = e0/s; g_gw[warp*2+1] = e1/s;
    }
}

// ---------------- MoE combine (top-2 weighted sum into residual) ----------------
__global__ void moe_combine() {
    int idx = blockIdx.x*blockDim.x + threadIdx.x;
    if (idx >= Nn*Cc) return;
    int n = idx / Cc;
    int e0 = g_sel[n*2], e1 = g_sel[n*2+1];
    float w0 = g_gw[n*2], w1 = g_gw[n*2+1];
    g_h[idx] += w0*g_moe[(size_t)e0*Nn*Cc + idx] + w1*g_moe[(size_t)e1*Nn*Cc + idx];
}

// ---------------- host launcher ----------------
extern "C" void kernel_launch(void* const* d_in, const int* in_sizes, int n_in,
                              void* d_out, int out_size) {
    (void)in_sizes; (void)n_in; (void)out_size;
    const int*   ids        = (const int*)  d_in[0];
    const float* tok        = (const float*)d_in[1];
    const float* pos        = (const float*)d_in[2];
    const float* attn_norm  = (const float*)d_in[3];
    const float* q_w        = (const float*)d_in[4];
    const float* k_w        = (const float*)d_in[5];
    const float* v_w        = (const float*)d_in[6];
    const float* o_w        = (const float*)d_in[7];
    const float* ffn_norm   = (const float*)d_in[8];
    const float* gate_w     = (const float*)d_in[9];
    const float* expert_w   = (const float*)d_in[10];
    const float* final_norm = (const float*)d_in[11];
    const float* out_w      = (const float*)d_in[12];
    float* out = (float*)d_out;

    float *h, *xn, *q, *k, *v, *att, *proj, *moe;
    cudaGetSymbolAddress((void**)&h,    g_h);
    cudaGetSymbolAddress((void**)&xn,   g_xn);
    cudaGetSymbolAddress((void**)&q,    g_q);
    cudaGetSymbolAddress((void**)&k,    g_k);
    cudaGetSymbolAddress((void**)&v,    g_v);
    cudaGetSymbolAddress((void**)&att,  g_att);
    cudaGetSymbolAddress((void**)&proj, g_proj);
    cudaGetSymbolAddress((void**)&moe,  g_moe);

    embed_kernel<<<(Nn*Cc + 255)/256, 256>>>(ids, tok, pos);

    for (int l = 0; l < Ll; l++) {
        // --- attention block ---
        rmsnorm_kernel<<<Nn, 256>>>(h, attn_norm + (size_t)l*Cc, xn);
        dim3 gq(Cc/128, Nn/128);
        sgemm_nt<<<gq, 256>>>(xn, q_w + (size_t)l*Cc*Cc, q, Nn, Cc, Cc, 0, 0);
        dim3 gkv(KVD/128, Nn/128);
        sgemm_nt<<<gkv, 256>>>(xn, k_w + (size_t)l*KVD*Cc, k, Nn, KVD, Cc, 0, 0);
        sgemm_nt<<<gkv, 256>>>(xn, v_w + (size_t)l*KVD*Cc, v, Nn, KVD, Cc, 0, 0);
        dim3 ga(Tt, Hh, Bb);
        attn_kernel<<<ga, 128>>>();
        sgemm_nt<<<gq, 256>>>(att, o_w + (size_t)l*Cc*Cc, proj, Nn, Cc, Cc, 0, 0);
        add_kernel<<<(Nn*Cc + 255)/256, 256>>>(h, proj, Nn*Cc);

        // --- MoE block ---
        rmsnorm_kernel<<<Nn, 256>>>(h, ffn_norm + (size_t)l*Cc, xn);
        gate_kernel<<<Nn/8, 256>>>(xn, gate_w + (size_t)l*Ee*Cc);
        dim3 ge(Cc/128, Nn/128, Ee);
        sgemm_nt<<<ge, 256>>>(xn, expert_w + (size_t)l*Ee*Cc*Cc, moe,
                              Nn, Cc, Cc, (size_t)Cc*Cc, (size_t)Nn*Cc);
        moe_combine<<<(Nn*Cc + 255)/256, 256>>>();
    }

    // --- final norm + vocab projection (the 67 GF GEMM) ---
    rmsnorm_kernel<<<Nn, 256>>>(h, final_norm, xn);
    dim3 gf(Vv/128, Nn/128);
    sgemm_nt<<<gf, 256>>>(xn, out_w, out, Nn, Vv, Cc, 0, 0);
}

// round 3
// speedup vs baseline: 1.5910x; 1.5910x over previous
#include <cuda_runtime.h>
#include <cuda_bf16.h>
#include <math.h>
#include <stdint.h>

#define Bb 2
#define Tt 1024
#define Cc 512
#define Hh 8
#define KVh 2
#define HD 64
#define Ll 2
#define Ee 8
#define TOPK 2
#define Vv 32000
#define Nn (Bb*Tt)        // 2048 tokens
#define KVD (KVh*HD)      // 128
#define QKVN (Cc + 2*KVD) // 768 fused qkv output width
#define EPSf 1e-6f

// ---------------- scratch (device globals; no allocation allowed) ----------------
__device__ float g_h[Nn*Cc];
__device__ float g_xn[Nn*Cc];
__device__ float g_qkv[Nn*QKVN];
__device__ float g_att[Nn*Cc];
__device__ float g_proj[Nn*Cc];
__device__ float g_moe[Ee*Nn*Cc];
__device__ int   g_sel[Nn*TOPK];
__device__ float g_gw[Nn*TOPK];
// bf16 split buffers
__device__ __nv_bfloat16 g_ah[Nn*Cc];
__device__ __nv_bfloat16 g_al[Nn*Cc];
__device__ __nv_bfloat16 g_wh[Vv*Cc];   // largest weight: out_w
__device__ __nv_bfloat16 g_wl[Vv*Cc];

// ---------------- embedding ----------------
__global__ void embed_kernel(const int* __restrict__ ids,
                             const float* __restrict__ tok,
                             const float* __restrict__ pos) {
    int idx = blockIdx.x * blockDim.x + threadIdx.x;
    if (idx >= Nn*Cc) return;
    int n = idx / Cc, c = idx - n*Cc;
    int t = n % Tt;
    g_h[idx] = tok[(size_t)ids[n]*Cc + c] + pos[(size_t)t*Cc + c];
}

// ---------------- rmsnorm (block per token) ----------------
__global__ void rmsnorm_kernel(const float* __restrict__ x,
                               const float* __restrict__ w,
                               float* __restrict__ y) {
    int n = blockIdx.x;
    const float* xr = x + (size_t)n*Cc;
    __shared__ float red[256];
    float s = 0.f;
    for (int c = threadIdx.x; c < Cc; c += 256) { float v = xr[c]; s += v*v; }
    red[threadIdx.x] = s; __syncthreads();
    for (int o = 128; o > 0; o >>= 1) {
        if (threadIdx.x < o) red[threadIdx.x] += red[threadIdx.x + o];
        __syncthreads();
    }
    float inv = rsqrtf(red[0] / (float)Cc + EPSf);
    for (int c = threadIdx.x; c < Cc; c += 256)
        y[(size_t)n*Cc + c] = xr[c] * inv * w[c];
}

// ---------------- fp32 -> (hi,lo) bf16 split, float4-vectorized ----------------
__global__ void split_kernel(const float* __restrict__ x,
                             __nv_bfloat16* __restrict__ hi,
                             __nv_bfloat16* __restrict__ lo, int n4) {
    int i = blockIdx.x*blockDim.x + threadIdx.x;
    if (i >= n4) return;
    float4 v = ((const float4*)x)[i];
    __nv_bfloat16 h0 = __float2bfloat16(v.x);
    __nv_bfloat16 h1 = __float2bfloat16(v.y);
    __nv_bfloat16 h2 = __float2bfloat16(v.z);
    __nv_bfloat16 h3 = __float2bfloat16(v.w);
    __nv_bfloat16 l0 = __float2bfloat16(v.x - __bfloat162float(h0));
    __nv_bfloat16 l1 = __float2bfloat16(v.y - __bfloat162float(h1));
    __nv_bfloat16 l2 = __float2bfloat16(v.z - __bfloat162float(h2));
    __nv_bfloat16 l3 = __float2bfloat16(v.w - __bfloat162float(h3));
    __nv_bfloat162* H = (__nv_bfloat162*)hi;
    __nv_bfloat162* L = (__nv_bfloat162*)lo;
    H[i*2]   = __nv_bfloat162{h0, h1};
    H[i*2+1] = __nv_bfloat162{h2, h3};
    L[i*2]   = __nv_bfloat162{l0, l1};
    L[i*2+1] = __nv_bfloat162{l2, l3};
}

// ---------------- mma helpers ----------------
__device__ __forceinline__ void ldsm_x4(uint32_t& r0, uint32_t& r1, uint32_t& r2, uint32_t& r3, uint32_t addr) {
    asm volatile("ldmatrix.sync.aligned.m8n8.x4.shared.b16 {%0,%1,%2,%3}, [%4];"
                 : "=r"(r0), "=r"(r1), "=r"(r2), "=r"(r3) : "r"(addr));
}
__device__ __forceinline__ void ldsm_x2(uint32_t& r0, uint32_t& r1, uint32_t addr) {
    asm volatile("ldmatrix.sync.aligned.m8n8.x2.shared.b16 {%0,%1}, [%2];"
                 : "=r"(r0), "=r"(r1) : "r"(addr));
}
__device__ __forceinline__ void mma16816(float* c, uint32_t a0, uint32_t a1, uint32_t a2, uint32_t a3,
                                         uint32_t b0, uint32_t b1) {
    asm volatile("mma.sync.aligned.m16n8k16.row.col.f32.bf16.bf16.f32 "
                 "{%0,%1,%2,%3}, {%4,%5,%6,%7}, {%8,%9}, {%0,%1,%2,%3};"
                 : "+f"(c[0]), "+f"(c[1]), "+f"(c[2]), "+f"(c[3])
                 : "r"(a0), "r"(a1), "r"(a2), "r"(a3), "r"(b0), "r"(b1));
}

// ---------------- bf16-split tensor-core GEMM (NT): C[M,N] = A[M,K] * B[N,K]^T ----
// C = Ah*Bh + Ah*Bl + Al*Bh (fp32 accum). 128x128 tile, BK=32, 256 threads (2x4 warps).
// Requires M%128==0, N%128==0, K%32==0.
__global__ __launch_bounds__(256)
void gemm_bf16_nt(const __nv_bfloat16* __restrict__ Ah, const __nv_bfloat16* __restrict__ Al,
                  const __nv_bfloat16* __restrict__ Bh, const __nv_bfloat16* __restrict__ Bl,
                  float* __restrict__ Cm, int M, int N, int K,
                  size_t strideB, size_t strideC) {
    Bh += (size_t)blockIdx.z * strideB;
    Bl += (size_t)blockIdx.z * strideB;
    Cm += (size_t)blockIdx.z * strideC;

    __shared__ __align__(16) __nv_bfloat16 sA[2][128][40]; // [hi/lo][row][k] pad->40
    __shared__ __align__(16) __nv_bfloat16 sB[2][128][40];

    int tid = threadIdx.x;
    int lane = tid & 31, wid = tid >> 5;
    int warpM = wid >> 2, warpN = wid & 3;    // 2 x 4 warp grid
    int row0 = blockIdx.y * 128, col0 = blockIdx.x * 128;

    float acc[4][4][4];
    #pragma unroll
    for (int mi = 0; mi < 4; mi++)
        #pragma unroll
        for (int ni = 0; ni < 4; ni++)
            #pragma unroll
            for (int r = 0; r < 4; r++) acc[mi][ni][r] = 0.f;

    int lr = tid >> 2;          // 0..63
    int lc = (tid & 3) * 8;     // 0,8,16,24

    // ldmatrix lane addressing
    int aRow = (lane & 15);
    int aColOff = (lane >> 4) * 8;
    int bRow = (lane & 7);
    int bColOff = ((lane >> 3) & 1) * 8;

    for (int k0 = 0; k0 < K; k0 += 32) {
        #pragma unroll
        for (int half = 0; half < 2; half++) {
            int r = lr + half*64;
            const uint4* pAh = (const uint4*)(Ah + (size_t)(row0 + r)*K + k0 + lc);
            const uint4* pAl = (const uint4*)(Al + (size_t)(row0 + r)*K + k0 + lc);
            const uint4* pBh = (const uint4*)(Bh + (size_t)(col0 + r)*K + k0 + lc);
            const uint4* pBl = (const uint4*)(Bl + (size_t)(col0 + r)*K + k0 + lc);
            *(uint4*)&sA[0][r][lc] = *pAh;
            *(uint4*)&sA[1][r][lc] = *pAl;
            *(uint4*)&sB[0][r][lc] = *pBh;
            *(uint4*)&sB[1][r][lc] = *pBl;
        }
        __syncthreads();

        #pragma unroll
        for (int ks = 0; ks < 32; ks += 16) {
            uint32_t bh[4][2], bl[4][2];
            #pragma unroll
            for (int ni = 0; ni < 4; ni++) {
                int brow = warpN*32 + ni*8 + bRow;
                uint32_t adH = (uint32_t)__cvta_generic_to_shared(&sB[0][brow][ks + bColOff]);
                uint32_t adL = (uint32_t)__cvta_generic_to_shared(&sB[1][brow][ks + bColOff]);
                ldsm_x2(bh[ni][0], bh[ni][1], adH);
                ldsm_x2(bl[ni][0], bl[ni][1], adL);
            }
            #pragma unroll
            for (int mi = 0; mi < 4; mi++) {
                int arow = warpM*64 + mi*16 + aRow;
                uint32_t ah0, ah1, ah2, ah3, al0, al1, al2, al3;
                uint32_t adH = (uint32_t)__cvta_generic_to_shared(&sA[0][arow][ks + aColOff]);
                uint32_t adL = (uint32_t)__cvta_generic_to_shared(&sA[1][arow][ks + aColOff]);
                ldsm_x4(ah0, ah1, ah2, ah3, adH);
                ldsm_x4(al0, al1, al2, al3, adL);
                #pragma unroll
                for (int ni = 0; ni < 4; ni++) {
                    mma16816(acc[mi][ni], ah0, ah1, ah2, ah3, bh[ni][0], bh[ni][1]);
                    mma16816(acc[mi][ni], ah0, ah1, ah2, ah3, bl[ni][0], bl[ni][1]);
                    mma16816(acc[mi][ni], al0, al1, al2, al3, bh[ni][0], bh[ni][1]);
                }
            }
        }
        __syncthreads();
    }

    // epilogue: c frag rows lane>>2 (+8), cols (lane&3)*2 (+1)
    #pragma unroll
    for (int mi = 0; mi < 4; mi++) {
        #pragma unroll
        for (int ni = 0; ni < 4; ni++) {
            int r = row0 + warpM*64 + mi*16 + (lane >> 2);
            int c = col0 + warpN*32 + ni*8 + (lane & 3)*2;
            float2 v0 = {acc[mi][ni][0], acc[mi][ni][1]};
            float2 v1 = {acc[mi][ni][2], acc[mi][ni][3]};
            *(float2*)&Cm[(size_t)r*N + c]       = v0;
            *(float2*)&Cm[(size_t)(r + 8)*N + c] = v1;
        }
    }
}

// ---------------- causal GQA attention on fused qkv buffer ----------------
__global__ void attn_kernel() {
    int qp = blockIdx.x, hh = blockIdx.y, b = blockIdx.z;
    int kvh = hh / (Hh / KVh);
    __shared__ float qs[HD];
    __shared__ float sc[Tt];
    __shared__ float red[128];
    int tid = threadIdx.x;

    const float* qrow = g_qkv + ((size_t)(b*Tt + qp))*QKVN + hh*HD;
    if (tid < HD) qs[tid] = qrow[tid];
    __syncthreads();

    int nk = qp + 1;
    float lmax = -1e30f;
    for (int k = tid; k < nk; k += 128) {
        const float* kr = g_qkv + ((size_t)(b*Tt + k))*QKVN + Cc + kvh*HD;
        float d = 0.f;
        #pragma unroll
        for (int i = 0; i < HD; i++) d += qs[i]*kr[i];
        d *= 0.125f;
        sc[k] = d;
        lmax = fmaxf(lmax, d);
    }
    red[tid] = lmax; __syncthreads();
    for (int o = 64; o > 0; o >>= 1) {
        if (tid < o) red[tid] = fmaxf(red[tid], red[tid + o]);
        __syncthreads();
    }
    float m = red[0];
    __syncthreads();

    float ls = 0.f;
    for (int k = tid; k < nk; k += 128) {
        float e = expf(sc[k] - m);
        sc[k] = e;
        ls += e;
    }
    red[tid] = ls; __syncthreads();
    for (int o = 64; o > 0; o >>= 1) {
        if (tid < o) red[tid] += red[tid + o];
        __syncthreads();
    }
    float inv = 1.f / red[0];
    __syncthreads();

    if (tid < HD) {
        float a = 0.f;
        const float* vbase = g_qkv + (size_t)b*Tt*QKVN + Cc + KVD + kvh*HD + tid;
        for (int k = 0; k < nk; k++) a += sc[k] * vbase[(size_t)k*QKVN];
        g_att[((size_t)(b*Tt + qp))*Cc + hh*HD + tid] = a * inv;
    }
}

// ---------------- residual add ----------------
__global__ void add_kernel(float* __restrict__ a, const float* __restrict__ b, int n) {
    int idx = blockIdx.x*blockDim.x + threadIdx.x;
    if (idx < n) a[idx] += b[idx];
}

// ---------------- gating: warp per token, top-2 + softmax (exact fp32) -------
__global__ void gate_kernel(const float* __restrict__ xn, const float* __restrict__ gw) {
    int warp = (blockIdx.x*blockDim.x + threadIdx.x) >> 5;
    int lane = threadIdx.x & 31;
    if (warp >= Nn) return;
    const float* xr = xn + (size_t)warp*Cc;
    float logits[Ee];
    #pragma unroll
    for (int e = 0; e < Ee; e++) {
        float s = 0.f;
        for (int c = lane; c < Cc; c += 32) s += xr[c]*gw[(size_t)e*Cc + c];
        #pragma unroll
        for (int o = 16; o > 0; o >>= 1) s += __shfl_down_sync(0xffffffffu, s, o);
        logits[e] = __shfl_sync(0xffffffffu, s, 0);
    }
    if (lane == 0) {
        int b0 = 0;
        #pragma unroll
        for (int e = 1; e < Ee; e++) if (logits[e] > logits[b0]) b0 = e;
        int b1 = -1;
        #pragma unroll
        for (int e = 0; e < Ee; e++) {
            if (e == b0) continue;
            if (b1 < 0 || logits[e] > logits[b1]) b1 = e;
        }
        float mm = logits[b0];
        float e0 = expf(logits[b0] - mm), e1 = expf(logits[b1] - mm);
        float s = e0 + e1;
        g_sel[warp*2]   = b0;   g_sel[warp*2+1] = b1;
        g_gw[warp*2]    = e0/s; g_gw[warp*2+1]  = e1/s;
    }
}

// ---------------- MoE combine ----------------
__global__ void moe_combine() {
    int idx = blockIdx.x*blockDim.x + threadIdx.x;
    if (idx >= Nn*Cc) return;
    int n = idx / Cc;
    int e0 = g_sel[n*2], e1 = g_sel[n*2+1];
    float w0 = g_gw[n*2], w1 = g_gw[n*2+1];
    g_h[idx] += w0*g_moe[(size_t)e0*Nn*Cc + idx] + w1*g_moe[(size_t)e1*Nn*Cc + idx];
}

// ---------------- host launcher ----------------
extern "C" void kernel_launch(void* const* d_in, const int* in_sizes, int n_in,
                              void* d_out, int out_size) {
    (void)in_sizes; (void)n_in; (void)out_size;
    const int*   ids        = (const int*)  d_in[0];
    const float* tok        = (const float*)d_in[1];
    const float* pos        = (const float*)d_in[2];
    const float* attn_norm  = (const float*)d_in[3];
    const float* q_w        = (const float*)d_in[4];
    const float* k_w        = (const float*)d_in[5];
    const float* v_w        = (const float*)d_in[6];
    const float* o_w        = (const float*)d_in[7];
    const float* ffn_norm   = (const float*)d_in[8];
    const float* gate_w     = (const float*)d_in[9];
    const float* expert_w   = (const float*)d_in[10];
    const float* final_norm = (const float*)d_in[11];
    const float* out_w      = (const float*)d_in[12];
    float* out = (float*)d_out;

    float *h, *xn, *qkv, *att, *proj, *moe;
    __nv_bfloat16 *ah, *al, *wh, *wl;
    cudaGetSymbolAddress((void**)&h,    g_h);
    cudaGetSymbolAddress((void**)&xn,   g_xn);
    cudaGetSymbolAddress((void**)&qkv,  g_qkv);
    cudaGetSymbolAddress((void**)&att,  g_att);
    cudaGetSymbolAddress((void**)&proj, g_proj);
    cudaGetSymbolAddress((void**)&moe,  g_moe);
    cudaGetSymbolAddress((void**)&ah,   g_ah);
    cudaGetSymbolAddress((void**)&al,   g_al);
    cudaGetSymbolAddress((void**)&wh,   g_wh);
    cudaGetSymbolAddress((void**)&wl,   g_wl);

    auto split = [](const float* src, __nv_bfloat16* hi, __nv_bfloat16* lo, int n) {
        int n4 = n / 4;
        split_kernel<<<(n4 + 255)/256, 256>>>(src, hi, lo, n4);
    };

    embed_kernel<<<(Nn*Cc + 255)/256, 256>>>(ids, tok, pos);

    for (int l = 0; l < Ll; l++) {
        // --- attention block ---
        rmsnorm_kernel<<<Nn, 256>>>(h, attn_norm + (size_t)l*Cc, xn);
        split(xn, ah, al, Nn*Cc);
        // fused qkv weights: rows [0,512)=q, [512,640)=k, [640,768)=v
        split(q_w + (size_t)l*Cc*Cc,  wh,                      wl,                      Cc*Cc);
        split(k_w + (size_t)l*KVD*Cc, wh + (size_t)Cc*Cc,      wl + (size_t)Cc*Cc,      KVD*Cc);
        split(v_w + (size_t)l*KVD*Cc, wh + (size_t)(Cc+KVD)*Cc, wl + (size_t)(Cc+KVD)*Cc, KVD*Cc);
        {
            dim3 g(QKVN/128, Nn/128);
            gemm_bf16_nt<<<g, 256>>>(ah, al, wh, wl, qkv, Nn, QKVN, Cc, 0, 0);
        }
        {
            dim3 ga(Tt, Hh, Bb);
            attn_kernel<<<ga, 128>>>();
        }
        split(att, ah, al, Nn*Cc);
        split(o_w + (size_t)l*Cc*Cc, wh, wl, Cc*Cc);
        {
            dim3 g(Cc/128, Nn/128);
            gemm_bf16_nt<<<g, 256>>>(ah, al, wh, wl, proj, Nn, Cc, Cc, 0, 0);
        }
        add_kernel<<<(Nn*Cc + 255)/256, 256>>>(h, proj, Nn*Cc);

        // --- MoE block ---
        rmsnorm_kernel<<<Nn, 256>>>(h, ffn_norm + (size_t)l*Cc, xn);
        gate_kernel<<<Nn/8, 256>>>(xn, gate_w + (size_t)l*Ee*Cc);
        split(xn, ah, al, Nn*Cc);
        split(expert_w + (size_t)l*Ee*Cc*Cc, wh, wl, Ee*Cc*Cc);
        {
            dim3 g(Cc/128, Nn/128, Ee);
            gemm_bf16_nt<<<g, 256>>>(ah, al, wh, wl, moe, Nn, Cc, Cc,
                                     (size_t)Cc*Cc, (size_t)Nn*Cc);
        }
        moe_combine<<<(Nn*Cc + 255)/256, 256>>>();
    }

    // --- final norm + vocab projection ---
    rmsnorm_kernel<<<Nn, 256>>>(h, final_norm, xn);
    split(xn, ah, al, Nn*Cc);
    split(out_w, wh, wl, Vv*Cc);
    {
        dim3 g(Vv/128, Nn/128);
        gemm_bf16_nt<<<g, 256>>>(ah, al, wh, wl, out, Nn, Vv, Cc, 0, 0);
    }
}